// round 2
// baseline (speedup 1.0000x reference)
#include <cuda_runtime.h>

#define N_NODES 100000
#define N_EDGES 50000
#define NNZ_TOT 500000
#define C 128

// -------- persistent scratch (no allocations allowed) --------
__device__ float g_xw[(size_t)N_NODES * C];    // 51.2 MB
__device__ float g_edge[(size_t)N_EDGES * C];  // 25.6 MB
__device__ float g_degn[N_NODES];
__device__ float g_dege[N_EDGES];
__device__ float g_dinv[N_NODES];
__device__ float g_binv[N_EDGES];

// -------- zero internal state (edge accumulator + degree counters) --------
__global__ void zero_state_kernel() {
    const float4 z = make_float4(0.f, 0.f, 0.f, 0.f);
    int i = blockIdx.x * blockDim.x + threadIdx.x;
    int stride = gridDim.x * blockDim.x;
    float4* pe = (float4*)g_edge;
    for (int j = i; j < (N_EDGES * C) / 4; j += stride) pe[j] = z;
    float4* pn = (float4*)g_degn;
    for (int j = i; j < N_NODES / 4; j += stride) pn[j] = z;
    float4* pg = (float4*)g_dege;
    for (int j = i; j < N_EDGES / 4; j += stride) pg[j] = z;
}

__global__ void zero_out_kernel(float4* __restrict__ out) {
    const float4 z = make_float4(0.f, 0.f, 0.f, 0.f);
    int i = blockIdx.x * blockDim.x + threadIdx.x;
    int stride = gridDim.x * blockDim.x;
    for (int j = i; j < (N_NODES * C) / 4; j += stride) out[j] = z;
}

// -------- degree computation --------
__global__ void degree_kernel(const int* __restrict__ nidx, const int* __restrict__ eidx) {
    int i = blockIdx.x * blockDim.x + threadIdx.x;
    if (i < NNZ_TOT) {
        atomicAdd(&g_degn[nidx[i]], 1.0f);
        atomicAdd(&g_dege[eidx[i]], 1.0f);
    }
}

__global__ void inv_kernel() {
    int i = blockIdx.x * blockDim.x + threadIdx.x;
    if (i < N_NODES) {
        float d = g_degn[i];
        g_dinv[i] = d > 0.f ? 1.f / d : 0.f;
    }
    if (i < N_EDGES) {
        float d = g_dege[i];
        g_binv[i] = d > 0.f ? 1.f / d : 0.f;
    }
}

// -------- SGEMM: g_xw[M,128] = x[M,128] @ W[128,128]  (BM=128,BN=128,BK=8,TM=TN=8) --------
__global__ __launch_bounds__(256) void gemm_xw_kernel(const float* __restrict__ A,
                                                      const float* __restrict__ B,
                                                      int M) {
    __shared__ float As[8][128];  // transposed A tile: As[k][m]
    __shared__ float Bs[8][128];  // Bs[k][n]

    const int t = threadIdx.x;
    const int brow = blockIdx.x * 128;

    // A-tile loader mapping: 128 rows x 8 cols, 256 threads x float4
    const int arow = t >> 1;           // 0..127
    const int acol = (t & 1) << 2;     // 0 or 4
    // B-tile loader mapping: 8 rows x 128 cols
    const int bld_r = t >> 5;          // 0..7
    const int bld_c = (t & 31) << 2;   // 0..124
    // compute mapping: 16x16 threads, 8x8 microtile each
    const int tx = t & 15;             // output col group
    const int ty = t >> 4;             // output row group

    const int g_arow = brow + arow;
    const bool a_valid = (g_arow < M);

    float acc[8][8];
#pragma unroll
    for (int i = 0; i < 8; i++)
#pragma unroll
        for (int j = 0; j < 8; j++) acc[i][j] = 0.f;

    for (int k0 = 0; k0 < 128; k0 += 8) {
        float4 av = make_float4(0.f, 0.f, 0.f, 0.f);
        if (a_valid) av = *(const float4*)&A[(size_t)g_arow * 128 + k0 + acol];
        As[acol + 0][arow] = av.x;
        As[acol + 1][arow] = av.y;
        As[acol + 2][arow] = av.z;
        As[acol + 3][arow] = av.w;

        float4 bv = *(const float4*)&B[(size_t)(k0 + bld_r) * 128 + bld_c];
        *(float4*)&Bs[bld_r][bld_c] = bv;

        __syncthreads();

#pragma unroll
        for (int k = 0; k < 8; k++) {
            float af[8], bf[8];
            *(float4*)&af[0] = *(const float4*)&As[k][ty * 8];
            *(float4*)&af[4] = *(const float4*)&As[k][ty * 8 + 4];
            *(float4*)&bf[0] = *(const float4*)&Bs[k][tx * 8];
            *(float4*)&bf[4] = *(const float4*)&Bs[k][tx * 8 + 4];
#pragma unroll
            for (int i = 0; i < 8; i++)
#pragma unroll
                for (int j = 0; j < 8; j++) acc[i][j] += af[i] * bf[j];
        }
        __syncthreads();
    }

#pragma unroll
    for (int i = 0; i < 8; i++) {
        int r = brow + ty * 8 + i;
        if (r < M) {
            float4 v0 = make_float4(acc[i][0], acc[i][1], acc[i][2], acc[i][3]);
            float4 v1 = make_float4(acc[i][4], acc[i][5], acc[i][6], acc[i][7]);
            *(float4*)&g_xw[(size_t)r * C + tx * 8] = v0;
            *(float4*)&g_xw[(size_t)r * C + tx * 8 + 4] = v1;
        }
    }
}

// -------- phase 1: edge_feat[e] += xw[n]  (warp per incidence) --------
__global__ __launch_bounds__(256) void scatter_ne_kernel(const int* __restrict__ nidx,
                                                         const int* __restrict__ eidx) {
    int g = blockIdx.x * blockDim.x + threadIdx.x;
    int w = g >> 5;
    int lane = g & 31;
    if (w >= NNZ_TOT) return;
    int n = __ldg(&nidx[w]);
    int e = __ldg(&eidx[w]);
    float4 v = *(const float4*)&g_xw[(size_t)n * C + lane * 4];
    float* d = &g_edge[(size_t)e * C + lane * 4];
    atomicAdd(d + 0, v.x);
    atomicAdd(d + 1, v.y);
    atomicAdd(d + 2, v.z);
    atomicAdd(d + 3, v.w);
}

// -------- phase 2: out[n] += edge_feat[e] * b_inv[e]  (warp per incidence) --------
__global__ __launch_bounds__(256) void scatter_en_kernel(const int* __restrict__ nidx,
                                                         const int* __restrict__ eidx,
                                                         float* __restrict__ out) {
    int g = blockIdx.x * blockDim.x + threadIdx.x;
    int w = g >> 5;
    int lane = g & 31;
    if (w >= NNZ_TOT) return;
    int n = __ldg(&nidx[w]);
    int e = __ldg(&eidx[w]);
    float bi = __ldg(&g_binv[e]);
    float4 v = *(const float4*)&g_edge[(size_t)e * C + lane * 4];
    float* d = &out[(size_t)n * C + lane * 4];
    atomicAdd(d + 0, v.x * bi);
    atomicAdd(d + 1, v.y * bi);
    atomicAdd(d + 2, v.z * bi);
    atomicAdd(d + 3, v.w * bi);
}

// -------- finalize: out = out * d_inv[row] + b[col] --------
__global__ __launch_bounds__(256) void finalize_kernel(float* __restrict__ out,
                                                       const float* __restrict__ b) {
    int i = blockIdx.x * blockDim.x + threadIdx.x;  // over N_NODES*32 float4s
    if (i >= N_NODES * (C / 4)) return;
    int row = i >> 5;
    int c4 = i & 31;
    float di = g_dinv[row];
    float4 v = ((float4*)out)[i];
    float4 bb = ((const float4*)b)[c4];
    v.x = v.x * di + bb.x;
    v.y = v.y * di + bb.y;
    v.z = v.z * di + bb.z;
    v.w = v.w * di + bb.w;
    ((float4*)out)[i] = v;
}

extern "C" void kernel_launch(void* const* d_in, const int* in_sizes, int n_in,
                              void* d_out, int out_size) {
    const float* x = (const float*)d_in[0];
    const int* hei = (const int*)d_in[1];
    const float* W = (const float*)d_in[2];
    const float* b = (const float*)d_in[3];
    const int* nidx = hei;             // hyperedge_index[0]
    const int* eidx = hei + NNZ_TOT;   // hyperedge_index[1]
    float* out = (float*)d_out;

    // zero accumulators + output
    zero_state_kernel<<<1480, 256>>>();
    zero_out_kernel<<<2960, 256>>>((float4*)out);

    // degrees + inverses
    degree_kernel<<<(NNZ_TOT + 255) / 256, 256>>>(nidx, eidx);
    inv_kernel<<<(N_NODES + 255) / 256, 256>>>();

    // xw = x @ W
    gemm_xw_kernel<<<(N_NODES + 127) / 128, 256>>>(x, W, N_NODES);

    // node -> edge
    scatter_ne_kernel<<<(NNZ_TOT * 32 + 255) / 256, 256>>>(nidx, eidx);

    // edge -> node (with B^-1 fused)
    scatter_en_kernel<<<(NNZ_TOT * 32 + 255) / 256, 256>>>(nidx, eidx, out);

    // out = out * D^-1 + b
    finalize_kernel<<<(N_NODES * (C / 4) + 255) / 256, 256>>>(out, b);
}

// round 3
// speedup vs baseline: 1.6296x; 1.6296x over previous
#include <cuda_runtime.h>

#define N_NODES 100000
#define N_EDGES 50000
#define NNZ_TOT 500000
#define C 128

// -------- persistent scratch (no allocations allowed) --------
__device__ float g_xw[(size_t)N_NODES * C];    // 51.2 MB
__device__ float g_edge[(size_t)N_EDGES * C];  // 25.6 MB
__device__ float g_degn[N_NODES];
__device__ float g_dege[N_EDGES];
__device__ float g_dinv[N_NODES];
__device__ float g_binv[N_EDGES];

__device__ __forceinline__ void red_add_v4(float* addr, float4 v) {
    asm volatile("red.global.add.v4.f32 [%0], {%1, %2, %3, %4};"
                 :: "l"(addr), "f"(v.x), "f"(v.y), "f"(v.z), "f"(v.w)
                 : "memory");
}

// -------- zero internal state (edge accumulator + degree counters) --------
__global__ void zero_state_kernel() {
    const float4 z = make_float4(0.f, 0.f, 0.f, 0.f);
    int i = blockIdx.x * blockDim.x + threadIdx.x;
    int stride = gridDim.x * blockDim.x;
    float4* pe = (float4*)g_edge;
    for (int j = i; j < (N_EDGES * C) / 4; j += stride) pe[j] = z;
    float4* pn = (float4*)g_degn;
    for (int j = i; j < N_NODES / 4; j += stride) pn[j] = z;
    float4* pg = (float4*)g_dege;
    for (int j = i; j < N_EDGES / 4; j += stride) pg[j] = z;
}

__global__ void zero_out_kernel(float4* __restrict__ out) {
    const float4 z = make_float4(0.f, 0.f, 0.f, 0.f);
    int i = blockIdx.x * blockDim.x + threadIdx.x;
    int stride = gridDim.x * blockDim.x;
    for (int j = i; j < (N_NODES * C) / 4; j += stride) out[j] = z;
}

// -------- degree computation --------
__global__ void degree_kernel(const int* __restrict__ nidx, const int* __restrict__ eidx) {
    int i = blockIdx.x * blockDim.x + threadIdx.x;
    if (i < NNZ_TOT) {
        atomicAdd(&g_degn[nidx[i]], 1.0f);
        atomicAdd(&g_dege[eidx[i]], 1.0f);
    }
}

__global__ void inv_kernel() {
    int i = blockIdx.x * blockDim.x + threadIdx.x;
    if (i < N_NODES) {
        float d = g_degn[i];
        g_dinv[i] = d > 0.f ? 1.f / d : 0.f;
    }
    if (i < N_EDGES) {
        float d = g_dege[i];
        g_binv[i] = d > 0.f ? 1.f / d : 0.f;
    }
}

// -------- SGEMM: g_xw[M,128] = x[M,128] @ W[128,128]  (BM=128,BN=128,BK=8,TM=TN=8) --------
__global__ __launch_bounds__(256) void gemm_xw_kernel(const float* __restrict__ A,
                                                      const float* __restrict__ B,
                                                      int M) {
    __shared__ float As[8][128];  // transposed A tile: As[k][m]
    __shared__ float Bs[8][128];  // Bs[k][n]

    const int t = threadIdx.x;
    const int brow = blockIdx.x * 128;

    const int arow = t >> 1;           // 0..127
    const int acol = (t & 1) << 2;     // 0 or 4
    const int bld_r = t >> 5;          // 0..7
    const int bld_c = (t & 31) << 2;   // 0..124
    const int tx = t & 15;             // output col group
    const int ty = t >> 4;             // output row group

    const int g_arow = brow + arow;
    const bool a_valid = (g_arow < M);

    float acc[8][8];
#pragma unroll
    for (int i = 0; i < 8; i++)
#pragma unroll
        for (int j = 0; j < 8; j++) acc[i][j] = 0.f;

    for (int k0 = 0; k0 < 128; k0 += 8) {
        float4 av = make_float4(0.f, 0.f, 0.f, 0.f);
        if (a_valid) av = *(const float4*)&A[(size_t)g_arow * 128 + k0 + acol];
        As[acol + 0][arow] = av.x;
        As[acol + 1][arow] = av.y;
        As[acol + 2][arow] = av.z;
        As[acol + 3][arow] = av.w;

        float4 bv = *(const float4*)&B[(size_t)(k0 + bld_r) * 128 + bld_c];
        *(float4*)&Bs[bld_r][bld_c] = bv;

        __syncthreads();

#pragma unroll
        for (int k = 0; k < 8; k++) {
            float af[8], bf[8];
            *(float4*)&af[0] = *(const float4*)&As[k][ty * 8];
            *(float4*)&af[4] = *(const float4*)&As[k][ty * 8 + 4];
            *(float4*)&bf[0] = *(const float4*)&Bs[k][tx * 8];
            *(float4*)&bf[4] = *(const float4*)&Bs[k][tx * 8 + 4];
#pragma unroll
            for (int i = 0; i < 8; i++)
#pragma unroll
                for (int j = 0; j < 8; j++) acc[i][j] += af[i] * bf[j];
        }
        __syncthreads();
    }

#pragma unroll
    for (int i = 0; i < 8; i++) {
        int r = brow + ty * 8 + i;
        if (r < M) {
            float4 v0 = make_float4(acc[i][0], acc[i][1], acc[i][2], acc[i][3]);
            float4 v1 = make_float4(acc[i][4], acc[i][5], acc[i][6], acc[i][7]);
            *(float4*)&g_xw[(size_t)r * C + tx * 8] = v0;
            *(float4*)&g_xw[(size_t)r * C + tx * 8 + 4] = v1;
        }
    }
}

// -------- phase 1: edge_feat[e] += xw[n]  (warp per incidence, v4 red) --------
__global__ __launch_bounds__(256) void scatter_ne_kernel(const int* __restrict__ nidx,
                                                         const int* __restrict__ eidx) {
    int g = blockIdx.x * blockDim.x + threadIdx.x;
    int w = g >> 5;
    int lane = g & 31;
    if (w >= NNZ_TOT) return;
    int n = __ldg(&nidx[w]);
    int e = __ldg(&eidx[w]);
    float4 v = __ldg((const float4*)&g_xw[(size_t)n * C + lane * 4]);
    red_add_v4(&g_edge[(size_t)e * C + lane * 4], v);
}

// -------- phase 2: out[n] += edge_feat[e] * b_inv[e]  (warp per incidence, v4 red) --------
__global__ __launch_bounds__(256) void scatter_en_kernel(const int* __restrict__ nidx,
                                                         const int* __restrict__ eidx,
                                                         float* __restrict__ out) {
    int g = blockIdx.x * blockDim.x + threadIdx.x;
    int w = g >> 5;
    int lane = g & 31;
    if (w >= NNZ_TOT) return;
    int n = __ldg(&nidx[w]);
    int e = __ldg(&eidx[w]);
    float bi = __ldg(&g_binv[e]);
    float4 v = __ldg((const float4*)&g_edge[(size_t)e * C + lane * 4]);
    v.x *= bi; v.y *= bi; v.z *= bi; v.w *= bi;
    red_add_v4(&out[(size_t)n * C + lane * 4], v);
}

// -------- finalize: out = out * d_inv[row] + b[col] --------
__global__ __launch_bounds__(256) void finalize_kernel(float* __restrict__ out,
                                                       const float* __restrict__ b) {
    int i = blockIdx.x * blockDim.x + threadIdx.x;  // over N_NODES*32 float4s
    if (i >= N_NODES * (C / 4)) return;
    int row = i >> 5;
    int c4 = i & 31;
    float di = g_dinv[row];
    float4 v = ((float4*)out)[i];
    float4 bb = ((const float4*)b)[c4];
    v.x = v.x * di + bb.x;
    v.y = v.y * di + bb.y;
    v.z = v.z * di + bb.z;
    v.w = v.w * di + bb.w;
    ((float4*)out)[i] = v;
}

extern "C" void kernel_launch(void* const* d_in, const int* in_sizes, int n_in,
                              void* d_out, int out_size) {
    const float* x = (const float*)d_in[0];
    const int* hei = (const int*)d_in[1];
    const float* W = (const float*)d_in[2];
    const float* b = (const float*)d_in[3];
    const int* nidx = hei;             // hyperedge_index[0]
    const int* eidx = hei + NNZ_TOT;   // hyperedge_index[1]
    float* out = (float*)d_out;

    // zero accumulators + output
    zero_state_kernel<<<1480, 256>>>();
    zero_out_kernel<<<2960, 256>>>((float4*)out);

    // degrees + inverses
    degree_kernel<<<(NNZ_TOT + 255) / 256, 256>>>(nidx, eidx);
    inv_kernel<<<(N_NODES + 255) / 256, 256>>>();

    // xw = x @ W
    gemm_xw_kernel<<<(N_NODES + 127) / 128, 256>>>(x, W, N_NODES);

    // node -> edge
    scatter_ne_kernel<<<(NNZ_TOT * 32 + 255) / 256, 256>>>(nidx, eidx);

    // edge -> node (with B^-1 fused)
    scatter_en_kernel<<<(NNZ_TOT * 32 + 255) / 256, 256>>>(nidx, eidx, out);

    // out = out * D^-1 + b
    finalize_kernel<<<(N_NODES * (C / 4) + 255) / 256, 256>>>(out, b);
}

// round 5
// speedup vs baseline: 2.1928x; 1.3456x over previous
#include <cuda_runtime.h>

#define N_NODES 100000
#define N_EDGES 50000
#define NNZ_TOT 500000
#define C 128

#define SCAN_B 1024

// -------- persistent scratch (no allocations allowed) --------
__device__ float g_xw[(size_t)N_NODES * C];    // 51.2 MB
__device__ float g_edge[(size_t)N_EDGES * C];  // 25.6 MB
__device__ int g_deg_n[N_NODES];
__device__ int g_deg_e[N_EDGES];
__device__ int g_start_n[N_NODES];
__device__ int g_start_e[N_EDGES];
__device__ int g_cur_n[N_NODES];
__device__ int g_cur_e[N_EDGES];
__device__ int g_adj_e[NNZ_TOT];   // per-edge list of node ids
__device__ int g_adj_n[NNZ_TOT];   // per-node list of edge ids
__device__ int g_bsum_n[(N_NODES + SCAN_B - 1) / SCAN_B];
__device__ int g_bsum_e[(N_EDGES + SCAN_B - 1) / SCAN_B];

// -------- zero degree + cursor counters --------
__global__ void zero_counts_kernel() {
    int i = blockIdx.x * blockDim.x + threadIdx.x;
    if (i < N_NODES) { g_deg_n[i] = 0; g_cur_n[i] = 0; }
    if (i < N_EDGES) { g_deg_e[i] = 0; g_cur_e[i] = 0; }
}

// -------- degree histogram --------
__global__ void degree_kernel(const int* __restrict__ nidx, const int* __restrict__ eidx) {
    int i = blockIdx.x * blockDim.x + threadIdx.x;
    if (i < NNZ_TOT) {
        atomicAdd(&g_deg_n[nidx[i]], 1);
        atomicAdd(&g_deg_e[eidx[i]], 1);
    }
}

// -------- two-level exclusive scan (arrays selected in DEVICE code) --------
__global__ __launch_bounds__(SCAN_B) void scan_block_kernel(int which, int n) {
    const int* deg = which ? g_deg_e : g_deg_n;
    int* excl = which ? g_start_e : g_start_n;
    int* bsum = which ? g_bsum_e : g_bsum_n;

    __shared__ int sm[SCAN_B];
    int tid = threadIdx.x;
    int gid = blockIdx.x * SCAN_B + tid;
    int v = (gid < n) ? deg[gid] : 0;
    sm[tid] = v;
    __syncthreads();
#pragma unroll
    for (int off = 1; off < SCAN_B; off <<= 1) {
        int t = (tid >= off) ? sm[tid - off] : 0;
        __syncthreads();
        sm[tid] += t;
        __syncthreads();
    }
    if (gid < n) excl[gid] = sm[tid] - v;
    if (tid == SCAN_B - 1) bsum[blockIdx.x] = sm[tid];
}

__global__ __launch_bounds__(128) void scan_top_kernel(int which, int n) {
    int* bsum = which ? g_bsum_e : g_bsum_n;
    __shared__ int sm[128];
    int tid = threadIdx.x;
    int v = (tid < n) ? bsum[tid] : 0;
    sm[tid] = v;
    __syncthreads();
#pragma unroll
    for (int off = 1; off < 128; off <<= 1) {
        int t = (tid >= off) ? sm[tid - off] : 0;
        __syncthreads();
        sm[tid] += t;
        __syncthreads();
    }
    if (tid < n) bsum[tid] = sm[tid] - v;  // exclusive
}

__global__ __launch_bounds__(SCAN_B) void scan_add_kernel(int which, int n) {
    int* excl = which ? g_start_e : g_start_n;
    const int* bsum = which ? g_bsum_e : g_bsum_n;
    int gid = blockIdx.x * SCAN_B + threadIdx.x;
    if (gid < n) excl[gid] += bsum[blockIdx.x];
}

// -------- fill CSR adjacency (counting-sort placement) --------
__global__ void fill_adj_kernel(const int* __restrict__ nidx, const int* __restrict__ eidx) {
    int i = blockIdx.x * blockDim.x + threadIdx.x;
    if (i >= NNZ_TOT) return;
    int n = nidx[i];
    int e = eidx[i];
    int pe = atomicAdd(&g_cur_e[e], 1);
    g_adj_e[g_start_e[e] + pe] = n;
    int pn = atomicAdd(&g_cur_n[n], 1);
    g_adj_n[g_start_n[n] + pn] = e;
}

// -------- SGEMM: g_xw[M,128] = x[M,128] @ W[128,128] --------
__global__ __launch_bounds__(256) void gemm_xw_kernel(const float* __restrict__ A,
                                                      const float* __restrict__ B,
                                                      int M) {
    __shared__ float As[8][128];
    __shared__ float Bs[8][128];

    const int t = threadIdx.x;
    const int brow = blockIdx.x * 128;

    const int arow = t >> 1;
    const int acol = (t & 1) << 2;
    const int bld_r = t >> 5;
    const int bld_c = (t & 31) << 2;
    const int tx = t & 15;
    const int ty = t >> 4;

    const int g_arow = brow + arow;
    const bool a_valid = (g_arow < M);

    float acc[8][8];
#pragma unroll
    for (int i = 0; i < 8; i++)
#pragma unroll
        for (int j = 0; j < 8; j++) acc[i][j] = 0.f;

    for (int k0 = 0; k0 < 128; k0 += 8) {
        float4 av = make_float4(0.f, 0.f, 0.f, 0.f);
        if (a_valid) av = *(const float4*)&A[(size_t)g_arow * 128 + k0 + acol];
        As[acol + 0][arow] = av.x;
        As[acol + 1][arow] = av.y;
        As[acol + 2][arow] = av.z;
        As[acol + 3][arow] = av.w;

        float4 bv = *(const float4*)&B[(size_t)(k0 + bld_r) * 128 + bld_c];
        *(float4*)&Bs[bld_r][bld_c] = bv;

        __syncthreads();

#pragma unroll
        for (int k = 0; k < 8; k++) {
            float af[8], bf[8];
            *(float4*)&af[0] = *(const float4*)&As[k][ty * 8];
            *(float4*)&af[4] = *(const float4*)&As[k][ty * 8 + 4];
            *(float4*)&bf[0] = *(const float4*)&Bs[k][tx * 8];
            *(float4*)&bf[4] = *(const float4*)&Bs[k][tx * 8 + 4];
#pragma unroll
            for (int i = 0; i < 8; i++)
#pragma unroll
                for (int j = 0; j < 8; j++) acc[i][j] += af[i] * bf[j];
        }
        __syncthreads();
    }

#pragma unroll
    for (int i = 0; i < 8; i++) {
        int r = brow + ty * 8 + i;
        if (r < M) {
            float4 v0 = make_float4(acc[i][0], acc[i][1], acc[i][2], acc[i][3]);
            float4 v1 = make_float4(acc[i][4], acc[i][5], acc[i][6], acc[i][7]);
            *(float4*)&g_xw[(size_t)r * C + tx * 8] = v0;
            *(float4*)&g_xw[(size_t)r * C + tx * 8 + 4] = v1;
        }
    }
}

// -------- phase 1: warp per edge; edge_feat[e] = (1/deg_e) * sum_{v in e} xw[v] --------
__global__ __launch_bounds__(256) void gather_edge_kernel() {
    int g = blockIdx.x * blockDim.x + threadIdx.x;
    int e = g >> 5;
    int lane = g & 31;
    if (e >= N_EDGES) return;
    int s = g_start_e[e];
    int d = g_deg_e[e];
    float4 acc = make_float4(0.f, 0.f, 0.f, 0.f);
    int j = 0;
    for (; j + 2 <= d; j += 2) {
        int v0 = g_adj_e[s + j];
        int v1 = g_adj_e[s + j + 1];
        float4 a = __ldg((const float4*)&g_xw[(size_t)v0 * C + lane * 4]);
        float4 b = __ldg((const float4*)&g_xw[(size_t)v1 * C + lane * 4]);
        acc.x += a.x + b.x;
        acc.y += a.y + b.y;
        acc.z += a.z + b.z;
        acc.w += a.w + b.w;
    }
    if (j < d) {
        int v0 = g_adj_e[s + j];
        float4 a = __ldg((const float4*)&g_xw[(size_t)v0 * C + lane * 4]);
        acc.x += a.x; acc.y += a.y; acc.z += a.z; acc.w += a.w;
    }
    float bi = (d > 0) ? (1.f / (float)d) : 0.f;
    acc.x *= bi; acc.y *= bi; acc.z *= bi; acc.w *= bi;
    *(float4*)&g_edge[(size_t)e * C + lane * 4] = acc;
}

// -------- phase 2: warp per node; out[n] = (1/deg_n) * sum_{e ni n} edge_feat[e] + b --------
__global__ __launch_bounds__(256) void gather_node_kernel(float* __restrict__ out,
                                                          const float* __restrict__ bias) {
    int g = blockIdx.x * blockDim.x + threadIdx.x;
    int nd = g >> 5;
    int lane = g & 31;
    if (nd >= N_NODES) return;
    int s = g_start_n[nd];
    int d = g_deg_n[nd];
    float4 acc = make_float4(0.f, 0.f, 0.f, 0.f);
    int j = 0;
    for (; j + 2 <= d; j += 2) {
        int e0 = g_adj_n[s + j];
        int e1 = g_adj_n[s + j + 1];
        float4 a = __ldg((const float4*)&g_edge[(size_t)e0 * C + lane * 4]);
        float4 b = __ldg((const float4*)&g_edge[(size_t)e1 * C + lane * 4]);
        acc.x += a.x + b.x;
        acc.y += a.y + b.y;
        acc.z += a.z + b.z;
        acc.w += a.w + b.w;
    }
    if (j < d) {
        int e0 = g_adj_n[s + j];
        float4 a = __ldg((const float4*)&g_edge[(size_t)e0 * C + lane * 4]);
        acc.x += a.x; acc.y += a.y; acc.z += a.z; acc.w += a.w;
    }
    float di = (d > 0) ? (1.f / (float)d) : 0.f;
    float4 bb = __ldg((const float4*)&bias[lane * 4]);
    acc.x = acc.x * di + bb.x;
    acc.y = acc.y * di + bb.y;
    acc.z = acc.z * di + bb.z;
    acc.w = acc.w * di + bb.w;
    *(float4*)&out[(size_t)nd * C + lane * 4] = acc;
}

extern "C" void kernel_launch(void* const* d_in, const int* in_sizes, int n_in,
                              void* d_out, int out_size) {
    const float* x = (const float*)d_in[0];
    const int* hei = (const int*)d_in[1];
    const float* W = (const float*)d_in[2];
    const float* b = (const float*)d_in[3];
    const int* nidx = hei;             // hyperedge_index[0]
    const int* eidx = hei + NNZ_TOT;   // hyperedge_index[1]
    float* out = (float*)d_out;

    const int NB_N = (N_NODES + SCAN_B - 1) / SCAN_B;  // 98
    const int NB_E = (N_EDGES + SCAN_B - 1) / SCAN_B;  // 49

    // CSR build
    zero_counts_kernel<<<(N_NODES + 255) / 256, 256>>>();
    degree_kernel<<<(NNZ_TOT + 255) / 256, 256>>>(nidx, eidx);

    scan_block_kernel<<<NB_N, SCAN_B>>>(0, N_NODES);
    scan_block_kernel<<<NB_E, SCAN_B>>>(1, N_EDGES);
    scan_top_kernel<<<1, 128>>>(0, NB_N);
    scan_top_kernel<<<1, 128>>>(1, NB_E);
    scan_add_kernel<<<NB_N, SCAN_B>>>(0, N_NODES);
    scan_add_kernel<<<NB_E, SCAN_B>>>(1, N_EDGES);

    fill_adj_kernel<<<(NNZ_TOT + 255) / 256, 256>>>(nidx, eidx);

    // xw = x @ W
    gemm_xw_kernel<<<(N_NODES + 127) / 128, 256>>>(x, W, N_NODES);

    // node -> edge (gather, fused B^-1)
    gather_edge_kernel<<<(N_EDGES * 32 + 255) / 256, 256>>>();

    // edge -> node (gather, fused D^-1 and bias)
    gather_node_kernel<<<(N_NODES * 32 + 255) / 256, 256>>>(out, b);
}

// round 6
// speedup vs baseline: 2.2141x; 1.0097x over previous
#include <cuda_runtime.h>
#include <cstdint>

#define N_NODES 100000
#define N_EDGES 50000
#define NNZ_TOT 500000
#define C 128

#define SCAN_B 1024
#define LDA 132  // 128 + 4 padding (floats)
#define SMEM_GEMM (2 * 128 * LDA * 4)

// -------- persistent scratch (no allocations allowed) --------
__device__ float g_xw[(size_t)N_NODES * C];    // 51.2 MB
__device__ float g_edge[(size_t)N_EDGES * C];  // 25.6 MB
__device__ int g_deg_n[N_NODES];
__device__ int g_deg_e[N_EDGES];
__device__ int g_start_n[N_NODES];
__device__ int g_start_e[N_EDGES];
__device__ int g_cur_n[N_NODES];
__device__ int g_cur_e[N_EDGES];
__device__ int g_adj_e[NNZ_TOT];   // per-edge list of node ids
__device__ int g_adj_n[NNZ_TOT];   // per-node list of edge ids
__device__ int g_bsum_n[(N_NODES + SCAN_B - 1) / SCAN_B];
__device__ int g_bsum_e[(N_EDGES + SCAN_B - 1) / SCAN_B];

#define NB_N ((N_NODES + SCAN_B - 1) / SCAN_B)  // 98
#define NB_E ((N_EDGES + SCAN_B - 1) / SCAN_B)  // 49

// -------- zero degree + cursor counters --------
__global__ void zero_counts_kernel() {
    int i = blockIdx.x * blockDim.x + threadIdx.x;
    if (i < N_NODES) { g_deg_n[i] = 0; g_cur_n[i] = 0; }
    if (i < N_EDGES) { g_deg_e[i] = 0; g_cur_e[i] = 0; }
}

// -------- degree histogram --------
__global__ void degree_kernel(const int* __restrict__ nidx, const int* __restrict__ eidx) {
    int i = blockIdx.x * blockDim.x + threadIdx.x;
    if (i < NNZ_TOT) {
        atomicAdd(&g_deg_n[nidx[i]], 1);
        atomicAdd(&g_deg_e[eidx[i]], 1);
    }
}

// -------- two-level exclusive scan (node + edge merged per launch) --------
__global__ __launch_bounds__(SCAN_B) void scan_block_kernel() {
    int which = (blockIdx.x >= NB_N);
    int bid = which ? (blockIdx.x - NB_N) : blockIdx.x;
    int n = which ? N_EDGES : N_NODES;
    const int* deg = which ? g_deg_e : g_deg_n;
    int* excl = which ? g_start_e : g_start_n;
    int* bsum = which ? g_bsum_e : g_bsum_n;

    __shared__ int sm[SCAN_B];
    int tid = threadIdx.x;
    int gid = bid * SCAN_B + tid;
    int v = (gid < n) ? deg[gid] : 0;
    sm[tid] = v;
    __syncthreads();
#pragma unroll
    for (int off = 1; off < SCAN_B; off <<= 1) {
        int t = (tid >= off) ? sm[tid - off] : 0;
        __syncthreads();
        sm[tid] += t;
        __syncthreads();
    }
    if (gid < n) excl[gid] = sm[tid] - v;
    if (tid == SCAN_B - 1) bsum[bid] = sm[tid];
}

__global__ __launch_bounds__(128) void scan_top_kernel() {
    int which = blockIdx.x;  // 0 = node, 1 = edge
    int n = which ? NB_E : NB_N;
    int* bsum = which ? g_bsum_e : g_bsum_n;
    __shared__ int sm[128];
    int tid = threadIdx.x;
    int v = (tid < n) ? bsum[tid] : 0;
    sm[tid] = v;
    __syncthreads();
#pragma unroll
    for (int off = 1; off < 128; off <<= 1) {
        int t = (tid >= off) ? sm[tid - off] : 0;
        __syncthreads();
        sm[tid] += t;
        __syncthreads();
    }
    if (tid < n) bsum[tid] = sm[tid] - v;  // exclusive
}

__global__ __launch_bounds__(SCAN_B) void scan_add_kernel() {
    int which = (blockIdx.x >= NB_N);
    int bid = which ? (blockIdx.x - NB_N) : blockIdx.x;
    int n = which ? N_EDGES : N_NODES;
    int* excl = which ? g_start_e : g_start_n;
    const int* bsum = which ? g_bsum_e : g_bsum_n;
    int gid = bid * SCAN_B + threadIdx.x;
    if (gid < n) excl[gid] += bsum[bid];
}

// -------- fill CSR adjacency (counting-sort placement) --------
__global__ void fill_adj_kernel(const int* __restrict__ nidx, const int* __restrict__ eidx) {
    int i = blockIdx.x * blockDim.x + threadIdx.x;
    if (i >= NNZ_TOT) return;
    int n = nidx[i];
    int e = eidx[i];
    int pe = atomicAdd(&g_cur_e[e], 1);
    g_adj_e[g_start_e[e] + pe] = n;
    int pn = atomicAdd(&g_cur_n[n], 1);
    g_adj_n[g_start_n[n] + pn] = e;
}

// -------- tf32 tensor GEMM with 3xTF32 compensation --------
__device__ __forceinline__ uint32_t f2tf32(float x) {
    uint32_t r;
    asm("cvt.rna.tf32.f32 %0, %1;" : "=r"(r) : "f"(x));
    return r;
}

__device__ __forceinline__ void split_tf32(float x, uint32_t& hi, uint32_t& lo) {
    hi = f2tf32(x);
    float r = x - __uint_as_float(hi);
    lo = f2tf32(r);
}

__device__ __forceinline__ void mma_tf32(float* d, const uint32_t* a, const uint32_t* b) {
    asm volatile(
        "mma.sync.aligned.m16n8k8.row.col.f32.tf32.tf32.f32 "
        "{%0,%1,%2,%3}, {%4,%5,%6,%7}, {%8,%9}, {%0,%1,%2,%3};\n"
        : "+f"(d[0]), "+f"(d[1]), "+f"(d[2]), "+f"(d[3])
        : "r"(a[0]), "r"(a[1]), "r"(a[2]), "r"(a[3]), "r"(b[0]), "r"(b[1]));
}

__global__ __launch_bounds__(256) void gemm_tf32_kernel(const float* __restrict__ A,
                                                        const float* __restrict__ W,
                                                        int M) {
    extern __shared__ float sm[];
    float* As = sm;              // [128][LDA]  row-major A tile
    float* Ws = sm + 128 * LDA;  // [128][LDA]  Ws[n][k] = W[k][n]

    const int t = threadIdx.x;
    const int warp = t >> 5;
    const int lane = t & 31;
    const int g = lane >> 2;      // groupID
    const int tc = lane & 3;      // thread-in-group
    const int warpM = warp & 3;   // 0..3  (32-row stripes)
    const int warpN = warp >> 2;  // 0..1  (64-col stripes)
    const int brow = blockIdx.x * 128;

    // load A tile (128x128), zero-pad beyond M
#pragma unroll
    for (int r = 0; r < 16; r++) {
        int idx = r * 256 + t;
        int m = idx >> 5;
        int kq = idx & 31;
        int gm = brow + m;
        float4 v = make_float4(0.f, 0.f, 0.f, 0.f);
        if (gm < M) v = *(const float4*)&A[(size_t)gm * 128 + kq * 4];
        *(float4*)&As[m * LDA + kq * 4] = v;
    }
    // load W transposed: Ws[n][k] = W[k][n]
#pragma unroll
    for (int r = 0; r < 16; r++) {
        int idx = r * 256 + t;
        int k = idx >> 5;
        int nq = idx & 31;
        float4 v = *(const float4*)&W[(size_t)k * 128 + nq * 4];
        Ws[(nq * 4 + 0) * LDA + k] = v.x;
        Ws[(nq * 4 + 1) * LDA + k] = v.y;
        Ws[(nq * 4 + 2) * LDA + k] = v.z;
        Ws[(nq * 4 + 3) * LDA + k] = v.w;
    }
    __syncthreads();

    float acc[2][8][4];
#pragma unroll
    for (int i = 0; i < 2; i++)
#pragma unroll
        for (int j = 0; j < 8; j++)
#pragma unroll
            for (int q = 0; q < 4; q++) acc[i][j][q] = 0.f;

#pragma unroll 1
    for (int ks = 0; ks < 16; ks++) {
        const int k0 = ks * 8;

        uint32_t ah[2][4], al[2][4];
#pragma unroll
        for (int mf = 0; mf < 2; mf++) {
            const float* base = &As[(warpM * 32 + mf * 16) * LDA + k0];
            float a0 = base[g * LDA + tc];
            float a1 = base[(g + 8) * LDA + tc];
            float a2 = base[g * LDA + tc + 4];
            float a3 = base[(g + 8) * LDA + tc + 4];
            split_tf32(a0, ah[mf][0], al[mf][0]);
            split_tf32(a1, ah[mf][1], al[mf][1]);
            split_tf32(a2, ah[mf][2], al[mf][2]);
            split_tf32(a3, ah[mf][3], al[mf][3]);
        }

        uint32_t bh[8][2], bl[8][2];
#pragma unroll
        for (int nf = 0; nf < 8; nf++) {
            const float* base = &Ws[(warpN * 64 + nf * 8 + g) * LDA + k0];
            float b0 = base[tc];
            float b1 = base[tc + 4];
            split_tf32(b0, bh[nf][0], bl[nf][0]);
            split_tf32(b1, bh[nf][1], bl[nf][1]);
        }

#pragma unroll
        for (int mf = 0; mf < 2; mf++)
#pragma unroll
            for (int nf = 0; nf < 8; nf++) {
                mma_tf32(acc[mf][nf], ah[mf], bh[nf]);
                mma_tf32(acc[mf][nf], ah[mf], bl[nf]);
                mma_tf32(acc[mf][nf], al[mf], bh[nf]);
            }
    }

    // store accumulators
#pragma unroll
    for (int mf = 0; mf < 2; mf++) {
        int r0 = brow + warpM * 32 + mf * 16 + g;
#pragma unroll
        for (int nf = 0; nf < 8; nf++) {
            int col = warpN * 64 + nf * 8 + tc * 2;
            if (r0 < M)
                *(float2*)&g_xw[(size_t)r0 * C + col] =
                    make_float2(acc[mf][nf][0], acc[mf][nf][1]);
            if (r0 + 8 < M)
                *(float2*)&g_xw[(size_t)(r0 + 8) * C + col] =
                    make_float2(acc[mf][nf][2], acc[mf][nf][3]);
        }
    }
}

// -------- phase 1: warp per edge; edge_feat[e] = (1/deg_e) * sum_{v in e} xw[v] --------
__global__ __launch_bounds__(256) void gather_edge_kernel() {
    int g = blockIdx.x * blockDim.x + threadIdx.x;
    int e = g >> 5;
    int lane = g & 31;
    if (e >= N_EDGES) return;
    int s = g_start_e[e];
    int d = g_deg_e[e];
    float4 acc = make_float4(0.f, 0.f, 0.f, 0.f);
    int j = 0;
    for (; j + 2 <= d; j += 2) {
        int v0 = g_adj_e[s + j];
        int v1 = g_adj_e[s + j + 1];
        float4 a = __ldg((const float4*)&g_xw[(size_t)v0 * C + lane * 4]);
        float4 b = __ldg((const float4*)&g_xw[(size_t)v1 * C + lane * 4]);
        acc.x += a.x + b.x;
        acc.y += a.y + b.y;
        acc.z += a.z + b.z;
        acc.w += a.w + b.w;
    }
    if (j < d) {
        int v0 = g_adj_e[s + j];
        float4 a = __ldg((const float4*)&g_xw[(size_t)v0 * C + lane * 4]);
        acc.x += a.x; acc.y += a.y; acc.z += a.z; acc.w += a.w;
    }
    float bi = (d > 0) ? (1.f / (float)d) : 0.f;
    acc.x *= bi; acc.y *= bi; acc.z *= bi; acc.w *= bi;
    *(float4*)&g_edge[(size_t)e * C + lane * 4] = acc;
}

// -------- phase 2: warp per node; out[n] = (1/deg_n) * sum_{e ni n} edge_feat[e] + b --------
__global__ __launch_bounds__(256) void gather_node_kernel(float* __restrict__ out,
                                                          const float* __restrict__ bias) {
    int g = blockIdx.x * blockDim.x + threadIdx.x;
    int nd = g >> 5;
    int lane = g & 31;
    if (nd >= N_NODES) return;
    int s = g_start_n[nd];
    int d = g_deg_n[nd];
    float4 acc = make_float4(0.f, 0.f, 0.f, 0.f);
    int j = 0;
    for (; j + 2 <= d; j += 2) {
        int e0 = g_adj_n[s + j];
        int e1 = g_adj_n[s + j + 1];
        float4 a = __ldg((const float4*)&g_edge[(size_t)e0 * C + lane * 4]);
        float4 b = __ldg((const float4*)&g_edge[(size_t)e1 * C + lane * 4]);
        acc.x += a.x + b.x;
        acc.y += a.y + b.y;
        acc.z += a.z + b.z;
        acc.w += a.w + b.w;
    }
    if (j < d) {
        int e0 = g_adj_n[s + j];
        float4 a = __ldg((const float4*)&g_edge[(size_t)e0 * C + lane * 4]);
        acc.x += a.x; acc.y += a.y; acc.z += a.z; acc.w += a.w;
    }
    float di = (d > 0) ? (1.f / (float)d) : 0.f;
    float4 bb = __ldg((const float4*)&bias[lane * 4]);
    acc.x = acc.x * di + bb.x;
    acc.y = acc.y * di + bb.y;
    acc.z = acc.z * di + bb.z;
    acc.w = acc.w * di + bb.w;
    *(float4*)&out[(size_t)nd * C + lane * 4] = acc;
}

extern "C" void kernel_launch(void* const* d_in, const int* in_sizes, int n_in,
                              void* d_out, int out_size) {
    const float* x = (const float*)d_in[0];
    const int* hei = (const int*)d_in[1];
    const float* W = (const float*)d_in[2];
    const float* b = (const float*)d_in[3];
    const int* nidx = hei;             // hyperedge_index[0]
    const int* eidx = hei + NNZ_TOT;   // hyperedge_index[1]
    float* out = (float*)d_out;

    // opt-in to 135 KB dynamic smem for the GEMM (not a stream op; capture-safe)
    cudaFuncSetAttribute(gemm_tf32_kernel, cudaFuncAttributeMaxDynamicSharedMemorySize,
                         SMEM_GEMM);

    // CSR build
    zero_counts_kernel<<<(N_NODES + 255) / 256, 256>>>();
    degree_kernel<<<(NNZ_TOT + 255) / 256, 256>>>(nidx, eidx);

    scan_block_kernel<<<NB_N + NB_E, SCAN_B>>>();
    scan_top_kernel<<<2, 128>>>();
    scan_add_kernel<<<NB_N + NB_E, SCAN_B>>>();

    fill_adj_kernel<<<(NNZ_TOT + 255) / 256, 256>>>(nidx, eidx);

    // xw = x @ W  (tf32 tensor cores, 3xTF32 compensation)
    gemm_tf32_kernel<<<(N_NODES + 127) / 128, 256, SMEM_GEMM>>>(x, W, N_NODES);

    // node -> edge (gather, fused B^-1)
    gather_edge_kernel<<<(N_EDGES * 32 + 255) / 256, 256>>>();

    // edge -> node (gather, fused D^-1 and bias)
    gather_node_kernel<<<(N_NODES * 32 + 255) / 256, 256>>>(out, b);
}

// round 7
// speedup vs baseline: 3.0620x; 1.3830x over previous
#include <cuda_runtime.h>
#include <cstdint>

#define N_NODES 100000
#define N_EDGES 50000
#define NNZ_TOT 500000
#define C 128

#define SCAN_B 1024
#define LDA 132  // 128 + 4 padding (floats)
#define SMEM_GEMM (2 * 128 * LDA * 4)

// -------- persistent scratch (no allocations allowed) --------
__device__ float g_eagg[(size_t)N_EDGES * C];  // 25.6 MB  (B^-1 H^T X)
__device__ float g_edge[(size_t)N_EDGES * C];  // 25.6 MB  (edge_feat = eagg @ W)
__device__ int g_deg_n[N_NODES];
__device__ int g_deg_e[N_EDGES];
__device__ int g_start_n[N_NODES];
__device__ int g_start_e[N_EDGES];
__device__ int g_cur_n[N_NODES];
__device__ int g_cur_e[N_EDGES];
__device__ int g_adj_e[NNZ_TOT];   // per-edge list of node ids
__device__ int g_adj_n[NNZ_TOT];   // per-node list of edge ids
__device__ int g_bsum_n[(N_NODES + SCAN_B - 1) / SCAN_B];
__device__ int g_bsum_e[(N_EDGES + SCAN_B - 1) / SCAN_B];

#define NB_N ((N_NODES + SCAN_B - 1) / SCAN_B)  // 98
#define NB_E ((N_EDGES + SCAN_B - 1) / SCAN_B)  // 49

// -------- zero degree + cursor counters --------
__global__ void zero_counts_kernel() {
    int i = blockIdx.x * blockDim.x + threadIdx.x;
    if (i < N_NODES) { g_deg_n[i] = 0; g_cur_n[i] = 0; }
    if (i < N_EDGES) { g_deg_e[i] = 0; g_cur_e[i] = 0; }
}

// -------- degree histogram --------
__global__ void degree_kernel(const int* __restrict__ nidx, const int* __restrict__ eidx) {
    int i = blockIdx.x * blockDim.x + threadIdx.x;
    if (i < NNZ_TOT) {
        atomicAdd(&g_deg_n[nidx[i]], 1);
        atomicAdd(&g_deg_e[eidx[i]], 1);
    }
}

// -------- two-level exclusive scan (node + edge merged per launch) --------
__global__ __launch_bounds__(SCAN_B) void scan_block_kernel() {
    int which = (blockIdx.x >= NB_N);
    int bid = which ? (blockIdx.x - NB_N) : blockIdx.x;
    int n = which ? N_EDGES : N_NODES;
    const int* deg = which ? g_deg_e : g_deg_n;
    int* excl = which ? g_start_e : g_start_n;
    int* bsum = which ? g_bsum_e : g_bsum_n;

    __shared__ int sm[SCAN_B];
    int tid = threadIdx.x;
    int gid = bid * SCAN_B + tid;
    int v = (gid < n) ? deg[gid] : 0;
    sm[tid] = v;
    __syncthreads();
#pragma unroll
    for (int off = 1; off < SCAN_B; off <<= 1) {
        int t = (tid >= off) ? sm[tid - off] : 0;
        __syncthreads();
        sm[tid] += t;
        __syncthreads();
    }
    if (gid < n) excl[gid] = sm[tid] - v;
    if (tid == SCAN_B - 1) bsum[bid] = sm[tid];
}

__global__ __launch_bounds__(128) void scan_top_kernel() {
    int which = blockIdx.x;  // 0 = node, 1 = edge
    int n = which ? NB_E : NB_N;
    int* bsum = which ? g_bsum_e : g_bsum_n;
    __shared__ int sm[128];
    int tid = threadIdx.x;
    int v = (tid < n) ? bsum[tid] : 0;
    sm[tid] = v;
    __syncthreads();
#pragma unroll
    for (int off = 1; off < 128; off <<= 1) {
        int t = (tid >= off) ? sm[tid - off] : 0;
        __syncthreads();
        sm[tid] += t;
        __syncthreads();
    }
    if (tid < n) bsum[tid] = sm[tid] - v;  // exclusive
}

__global__ __launch_bounds__(SCAN_B) void scan_add_kernel() {
    int which = (blockIdx.x >= NB_N);
    int bid = which ? (blockIdx.x - NB_N) : blockIdx.x;
    int n = which ? N_EDGES : N_NODES;
    int* excl = which ? g_start_e : g_start_n;
    const int* bsum = which ? g_bsum_e : g_bsum_n;
    int gid = bid * SCAN_B + threadIdx.x;
    if (gid < n) excl[gid] += bsum[bid];
}

// -------- fill CSR adjacency (counting-sort placement) --------
__global__ void fill_adj_kernel(const int* __restrict__ nidx, const int* __restrict__ eidx) {
    int i = blockIdx.x * blockDim.x + threadIdx.x;
    if (i >= NNZ_TOT) return;
    int n = nidx[i];
    int e = eidx[i];
    int pe = atomicAdd(&g_cur_e[e], 1);
    g_adj_e[g_start_e[e] + pe] = n;
    int pn = atomicAdd(&g_cur_n[n], 1);
    g_adj_n[g_start_n[n] + pn] = e;
}

// -------- phase 1: warp per edge; eagg[e] = (1/deg_e) * sum_{v in e} x[v] --------
__global__ __launch_bounds__(256) void gather_edge_kernel(const float* __restrict__ x) {
    int g = blockIdx.x * blockDim.x + threadIdx.x;
    int e = g >> 5;
    int lane = g & 31;
    if (e >= N_EDGES) return;
    int s = g_start_e[e];
    int d = g_deg_e[e];
    float4 acc = make_float4(0.f, 0.f, 0.f, 0.f);
    int j = 0;
    for (; j + 2 <= d; j += 2) {
        int v0 = g_adj_e[s + j];
        int v1 = g_adj_e[s + j + 1];
        float4 a = __ldg((const float4*)&x[(size_t)v0 * C + lane * 4]);
        float4 b = __ldg((const float4*)&x[(size_t)v1 * C + lane * 4]);
        acc.x += a.x + b.x;
        acc.y += a.y + b.y;
        acc.z += a.z + b.z;
        acc.w += a.w + b.w;
    }
    if (j < d) {
        int v0 = g_adj_e[s + j];
        float4 a = __ldg((const float4*)&x[(size_t)v0 * C + lane * 4]);
        acc.x += a.x; acc.y += a.y; acc.z += a.z; acc.w += a.w;
    }
    float bi = (d > 0) ? (1.f / (float)d) : 0.f;
    acc.x *= bi; acc.y *= bi; acc.z *= bi; acc.w *= bi;
    *(float4*)&g_eagg[(size_t)e * C + lane * 4] = acc;
}

// -------- tf32 tensor GEMM with 3xTF32 compensation: g_edge = g_eagg @ W --------
__device__ __forceinline__ uint32_t f2tf32(float x) {
    uint32_t r;
    asm("cvt.rna.tf32.f32 %0, %1;" : "=r"(r) : "f"(x));
    return r;
}

__device__ __forceinline__ void split_tf32(float x, uint32_t& hi, uint32_t& lo) {
    hi = f2tf32(x);
    float r = x - __uint_as_float(hi);
    lo = f2tf32(r);
}

__device__ __forceinline__ void mma_tf32(float* d, const uint32_t* a, const uint32_t* b) {
    asm volatile(
        "mma.sync.aligned.m16n8k8.row.col.f32.tf32.tf32.f32 "
        "{%0,%1,%2,%3}, {%4,%5,%6,%7}, {%8,%9}, {%0,%1,%2,%3};\n"
        : "+f"(d[0]), "+f"(d[1]), "+f"(d[2]), "+f"(d[3])
        : "r"(a[0]), "r"(a[1]), "r"(a[2]), "r"(a[3]), "r"(b[0]), "r"(b[1]));
}

__global__ __launch_bounds__(256) void gemm_tf32_kernel(const float* __restrict__ W,
                                                        int M) {
    extern __shared__ float sm[];
    float* As = sm;              // [128][LDA]  row-major A tile (edge_agg)
    float* Ws = sm + 128 * LDA;  // [128][LDA]  Ws[n][k] = W[k][n]

    const int t = threadIdx.x;
    const int warp = t >> 5;
    const int lane = t & 31;
    const int g = lane >> 2;      // groupID
    const int tc = lane & 3;      // thread-in-group
    const int warpM = warp & 3;   // 0..3  (32-row stripes)
    const int warpN = warp >> 2;  // 0..1  (64-col stripes)
    const int brow = blockIdx.x * 128;

    // load A tile (128x128), zero-pad beyond M
#pragma unroll
    for (int r = 0; r < 16; r++) {
        int idx = r * 256 + t;
        int m = idx >> 5;
        int kq = idx & 31;
        int gm = brow + m;
        float4 v = make_float4(0.f, 0.f, 0.f, 0.f);
        if (gm < M) v = *(const float4*)&g_eagg[(size_t)gm * 128 + kq * 4];
        *(float4*)&As[m * LDA + kq * 4] = v;
    }
    // load W transposed: Ws[n][k] = W[k][n]
#pragma unroll
    for (int r = 0; r < 16; r++) {
        int idx = r * 256 + t;
        int k = idx >> 5;
        int nq = idx & 31;
        float4 v = *(const float4*)&W[(size_t)k * 128 + nq * 4];
        Ws[(nq * 4 + 0) * LDA + k] = v.x;
        Ws[(nq * 4 + 1) * LDA + k] = v.y;
        Ws[(nq * 4 + 2) * LDA + k] = v.z;
        Ws[(nq * 4 + 3) * LDA + k] = v.w;
    }
    __syncthreads();

    float acc[2][8][4];
#pragma unroll
    for (int i = 0; i < 2; i++)
#pragma unroll
        for (int j = 0; j < 8; j++)
#pragma unroll
            for (int q = 0; q < 4; q++) acc[i][j][q] = 0.f;

#pragma unroll 1
    for (int ks = 0; ks < 16; ks++) {
        const int k0 = ks * 8;

        uint32_t ah[2][4], al[2][4];
#pragma unroll
        for (int mf = 0; mf < 2; mf++) {
            const float* base = &As[(warpM * 32 + mf * 16) * LDA + k0];
            float a0 = base[g * LDA + tc];
            float a1 = base[(g + 8) * LDA + tc];
            float a2 = base[g * LDA + tc + 4];
            float a3 = base[(g + 8) * LDA + tc + 4];
            split_tf32(a0, ah[mf][0], al[mf][0]);
            split_tf32(a1, ah[mf][1], al[mf][1]);
            split_tf32(a2, ah[mf][2], al[mf][2]);
            split_tf32(a3, ah[mf][3], al[mf][3]);
        }

        uint32_t bh[8][2], bl[8][2];
#pragma unroll
        for (int nf = 0; nf < 8; nf++) {
            const float* base = &Ws[(warpN * 64 + nf * 8 + g) * LDA + k0];
            float b0 = base[tc];
            float b1 = base[tc + 4];
            split_tf32(b0, bh[nf][0], bl[nf][0]);
            split_tf32(b1, bh[nf][1], bl[nf][1]);
        }

#pragma unroll
        for (int mf = 0; mf < 2; mf++)
#pragma unroll
            for (int nf = 0; nf < 8; nf++) {
                mma_tf32(acc[mf][nf], ah[mf], bh[nf]);
                mma_tf32(acc[mf][nf], ah[mf], bl[nf]);
                mma_tf32(acc[mf][nf], al[mf], bh[nf]);
            }
    }

    // store accumulators to g_edge
#pragma unroll
    for (int mf = 0; mf < 2; mf++) {
        int r0 = brow + warpM * 32 + mf * 16 + g;
#pragma unroll
        for (int nf = 0; nf < 8; nf++) {
            int col = warpN * 64 + nf * 8 + tc * 2;
            if (r0 < M)
                *(float2*)&g_edge[(size_t)r0 * C + col] =
                    make_float2(acc[mf][nf][0], acc[mf][nf][1]);
            if (r0 + 8 < M)
                *(float2*)&g_edge[(size_t)(r0 + 8) * C + col] =
                    make_float2(acc[mf][nf][2], acc[mf][nf][3]);
        }
    }
}

// -------- phase 2: warp per node; out[n] = (1/deg_n) * sum_{e ni n} edge_feat[e] + b --------
__global__ __launch_bounds__(256) void gather_node_kernel(float* __restrict__ out,
                                                          const float* __restrict__ bias) {
    int g = blockIdx.x * blockDim.x + threadIdx.x;
    int nd = g >> 5;
    int lane = g & 31;
    if (nd >= N_NODES) return;
    int s = g_start_n[nd];
    int d = g_deg_n[nd];
    float4 acc = make_float4(0.f, 0.f, 0.f, 0.f);
    int j = 0;
    for (; j + 2 <= d; j += 2) {
        int e0 = g_adj_n[s + j];
        int e1 = g_adj_n[s + j + 1];
        float4 a = __ldg((const float4*)&g_edge[(size_t)e0 * C + lane * 4]);
        float4 b = __ldg((const float4*)&g_edge[(size_t)e1 * C + lane * 4]);
        acc.x += a.x + b.x;
        acc.y += a.y + b.y;
        acc.z += a.z + b.z;
        acc.w += a.w + b.w;
    }
    if (j < d) {
        int e0 = g_adj_n[s + j];
        float4 a = __ldg((const float4*)&g_edge[(size_t)e0 * C + lane * 4]);
        acc.x += a.x; acc.y += a.y; acc.z += a.z; acc.w += a.w;
    }
    float di = (d > 0) ? (1.f / (float)d) : 0.f;
    float4 bb = __ldg((const float4*)&bias[lane * 4]);
    acc.x = acc.x * di + bb.x;
    acc.y = acc.y * di + bb.y;
    acc.z = acc.z * di + bb.z;
    acc.w = acc.w * di + bb.w;
    *(float4*)&out[(size_t)nd * C + lane * 4] = acc;
}

extern "C" void kernel_launch(void* const* d_in, const int* in_sizes, int n_in,
                              void* d_out, int out_size) {
    const float* x = (const float*)d_in[0];
    const int* hei = (const int*)d_in[1];
    const float* W = (const float*)d_in[2];
    const float* b = (const float*)d_in[3];
    const int* nidx = hei;             // hyperedge_index[0]
    const int* eidx = hei + NNZ_TOT;   // hyperedge_index[1]
    float* out = (float*)d_out;

    // opt-in to 135 KB dynamic smem for the GEMM (not a stream op; capture-safe)
    cudaFuncSetAttribute(gemm_tf32_kernel, cudaFuncAttributeMaxDynamicSharedMemorySize,
                         SMEM_GEMM);

    // CSR build
    zero_counts_kernel<<<(N_NODES + 255) / 256, 256>>>();
    degree_kernel<<<(NNZ_TOT + 255) / 256, 256>>>(nidx, eidx);

    scan_block_kernel<<<NB_N + NB_E, SCAN_B>>>();
    scan_top_kernel<<<2, 128>>>();
    scan_add_kernel<<<NB_N + NB_E, SCAN_B>>>();

    fill_adj_kernel<<<(NNZ_TOT + 255) / 256, 256>>>(nidx, eidx);

    // node -> edge aggregation of RAW x (fused B^-1): eagg = B^-1 H^T X
    gather_edge_kernel<<<(N_EDGES * 32 + 255) / 256, 256>>>(x);

    // edge_feat = eagg @ W  (tf32 tensor cores, 3xTF32 compensation; 50k rows)
    gemm_tf32_kernel<<<(N_EDGES + 127) / 128, 256, SMEM_GEMM>>>(W, N_EDGES);

    // edge -> node (gather, fused D^-1 and bias)
    gather_node_kernel<<<(N_NODES * 32 + 255) / 256, 256>>>(out, b);
}